// round 17
// baseline (speedup 1.0000x reference)
#include <cuda_runtime.h>
#include <cuda_bf16.h>
#include <math.h>
#include <stdint.h>

#define B_ 256
#define T_ 512
#define D_ 256
#define A_ 50
#define NP 56          // padded N (multiple of 8)
#define ROWS 128       // M tile per CTA (4 warps x 32 rows)
#define KC 16          // K chunk per warp-private stage
#define NCHUNK (D_ / KC)
#define BPITCH 264     // full-K B pitch in bf16 (528B rows: aligned + LDSM conflict-free)
#define APITCH 24      // warp-private A pitch in bf16 (48B rows: aligned + conflict-free)

typedef unsigned long long u64;

__device__ __align__(16) float g_pool_part[(B_ * T_ / ROWS) * D_];
__device__ float g_esum_part[B_ * T_ / ROWS];
__device__ int   g_cnt[B_];
__device__ __align__(16) __nv_bfloat16 g_wtb[NP * D_];   // W^T [n][k] bf16

__device__ __forceinline__ uint32_t smem_u32(const void* p) {
    uint32_t a;
    asm("{ .reg .u64 t; cvta.to.shared.u64 t, %1; cvt.u32.u64 %0, t; }" : "=r"(a) : "l"(p));
    return a;
}
__device__ __forceinline__ void ldx4(uint32_t* r, uint32_t addr) {
    asm volatile("ldmatrix.sync.aligned.m8n8.x4.shared.b16 {%0,%1,%2,%3}, [%4];"
                 : "=r"(r[0]), "=r"(r[1]), "=r"(r[2]), "=r"(r[3]) : "r"(addr));
}
__device__ __forceinline__ void ldx2(uint32_t* r, uint32_t addr) {
    asm volatile("ldmatrix.sync.aligned.m8n8.x2.shared.b16 {%0,%1}, [%2];"
                 : "=r"(r[0]), "=r"(r[1]) : "r"(addr));
}
__device__ __forceinline__ void mma16816(float* d, const uint32_t* a, const uint32_t* b) {
    asm volatile(
        "mma.sync.aligned.m16n8k16.row.col.f32.bf16.bf16.f32 "
        "{%0,%1,%2,%3}, {%4,%5,%6,%7}, {%8,%9}, {%0,%1,%2,%3};"
        : "+f"(d[0]), "+f"(d[1]), "+f"(d[2]), "+f"(d[3])
        : "r"(a[0]), "r"(a[1]), "r"(a[2]), "r"(a[3]), "r"(b[0]), "r"(b[1]));
}
__device__ __forceinline__ uint32_t pack_bf2(float vx, float vy) {
    uint32_t p;
    asm("cvt.rn.bf16x2.f32 %0, %1, %2;" : "=r"(p) : "f"(vy), "f"(vx));
    return p;
}
__device__ __forceinline__ float tanh_fast(float v) {
    float r;
    asm("tanh.approx.f32 %0, %1;" : "=f"(r) : "f"(v));
    return r;
}
#define CPASYNC16(sm_, gm_) \
    asm volatile("cp.async.cg.shared.global [%0], [%1], 16;" :: "r"(sm_), "l"(gm_))
#define CPCOMMIT() asm volatile("cp.async.commit_group;" ::: "memory")
#define CPWAIT0()  asm volatile("cp.async.wait_group 0;"  ::: "memory")

struct __align__(16) Smem {
    __nv_bfloat16 b[NP * BPITCH];         // 29568 B : full-K B tile
    __nv_bfloat16 aw[4][2][32 * APITCH];  // 4 warps x 2 bufs x 1536 B = 12288 B
    float sb[NP], su[NP];
    float se[ROWS];
    float wsum[4];
    float pp[64][4];
    int   is_last;
};

// Prep: W^T padded bf16 + zero batch counters.
__global__ __launch_bounds__(512) void prep_kernel(const float* __restrict__ W)
{
    int i = blockIdx.x * 512 + threadIdx.x;   // grid covers NP*D_ = 14336
    if (i < B_) g_cnt[i] = 0;
    if (i < NP * D_) {
        int n = i / D_, k = i - n * D_;
        float w = (n < A_) ? W[k * A_ + n] : 0.0f;
        g_wtb[i] = __float2bfloat16(w);
    }
}

__global__ __launch_bounds__(128, 4) void score_pool_mma(
    const float* __restrict__ x, const float* __restrict__ bias,
    const float* __restrict__ u, float* __restrict__ out)
{
    __shared__ Smem sm;

    const int tid  = threadIdx.x;
    const int wid  = tid >> 5;
    const int lane = tid & 31;
    const int row0 = blockIdx.x * ROWS;
    const int b    = blockIdx.x >> 2;

    // ---- preload full B (once) + params ----
    {
        const char* ghb = (const char*)g_wtb;
        const uint32_t bB = smem_u32(sm.b);
        #pragma unroll
        for (int j = 0; j < 14; ++j) {
            int s = j * 128 + tid;            // 1792 16B slots
            int n = s >> 5;
            int q = (s & 31) * 16;
            CPASYNC16(bB + (uint32_t)(n * (BPITCH * 2) + q), ghb + (u64)(n * 512 + q));
        }
        CPCOMMIT();
    }
    if (tid < NP) {
        sm.sb[tid] = (tid < A_) ? bias[tid] : 0.0f;
        sm.su[tid] = (tid < A_) ? u[tid]    : 0.0f;
    }
    CPWAIT0();
    __syncthreads();   // B + params visible; last CTA-wide barrier until epilogue

    float acc[2][7][4];
    #pragma unroll
    for (int mt = 0; mt < 2; ++mt)
        #pragma unroll
        for (int nt = 0; nt < 7; ++nt)
            #pragma unroll
            for (int q = 0; q < 4; ++q) acc[mt][nt][q] = 0.0f;

    // ldmatrix per-lane address components.
    const int sub      = lane >> 3;
    const int arow_off = (sub & 1) * 8 + (lane & 7);
    const int ak_off   = (sub >> 1) * 8;
    const int bn_off   = lane & 7;
    const int bk_off   = ((lane >> 3) & 1) * 8;

    // Warp-private A staging: 32 rows x 16 cols; lane -> 4 float4.
    const int ar  = lane >> 2;                 // row within 8-row group (+8 per it)
    const int ac4 = (lane & 3) << 2;           // col 0,4,8,12
    const float* xw = x + (size_t)(row0 + wid * 32) * D_;

    float4 apref[4];
    auto ldg_a = [&](int kc) {
        #pragma unroll
        for (int it = 0; it < 4; ++it)
            apref[it] = *(const float4*)(xw + (size_t)(it * 8 + ar) * D_ + kc * KC + ac4);
    };
    auto sts_a = [&](int buf) {
        #pragma unroll
        for (int it = 0; it < 4; ++it) {
            uint2 p;
            p.x = pack_bf2(apref[it].x, apref[it].y);
            p.y = pack_bf2(apref[it].z, apref[it].w);
            *(uint2*)&sm.aw[wid][buf][(it * 8 + ar) * APITCH + ac4] = p;
        }
    };

    const uint32_t bB = smem_u32(sm.b);

    // ---- prologue: stage chunk 0 (warp-local) ----
    ldg_a(0);
    sts_a(0);
    __syncwarp();

    for (int kc = 0; kc < NCHUNK; ++kc) {
        const int cur = kc & 1;

        if (kc + 1 < NCHUNK) ldg_a(kc + 1);   // LDG latency overlaps MMA below

        // ---- MMA on warp-private buffer (no CTA barrier)
        const uint32_t aBw = smem_u32(sm.aw[wid][cur]);
        uint32_t bhf[7][2];
        #pragma unroll
        for (int nt = 0; nt < 7; ++nt) {
            uint32_t off = (uint32_t)(((nt * 8 + bn_off) * BPITCH + kc * KC + bk_off) * 2);
            ldx2(bhf[nt], bB + off);
        }
        #pragma unroll
        for (int mt = 0; mt < 2; ++mt) {
            uint32_t off = (uint32_t)(((mt * 16 + arow_off) * APITCH + ak_off) * 2);
            uint32_t av[4];
            ldx4(av, aBw + off);
            #pragma unroll
            for (int nt = 0; nt < 7; ++nt)
                mma16816(acc[mt][nt], av, bhf[nt]);
        }

        if (kc + 1 < NCHUNK) {
            sts_a(cur ^ 1);
            __syncwarp();
        }
    }

    // ---- epilogue: scores.
    #pragma unroll
    for (int mt = 0; mt < 2; ++mt) {
        float plo = 0.0f, phi = 0.0f;
        #pragma unroll
        for (int nt = 0; nt < 7; ++nt) {
            int c = nt * 8 + 2 * (lane & 3);
            plo += tanh_fast(acc[mt][nt][0] + sm.sb[c])     * sm.su[c];
            plo += tanh_fast(acc[mt][nt][1] + sm.sb[c + 1]) * sm.su[c + 1];
            phi += tanh_fast(acc[mt][nt][2] + sm.sb[c])     * sm.su[c];
            phi += tanh_fast(acc[mt][nt][3] + sm.sb[c + 1]) * sm.su[c + 1];
        }
        plo += __shfl_xor_sync(0xFFFFFFFFu, plo, 1);
        plo += __shfl_xor_sync(0xFFFFFFFFu, plo, 2);
        phi += __shfl_xor_sync(0xFFFFFFFFu, phi, 1);
        phi += __shfl_xor_sync(0xFFFFFFFFu, phi, 2);
        if ((lane & 3) == 0) {
            int r = wid * 32 + mt * 16 + (lane >> 2);
            sm.se[r]     = __expf(plo);
            sm.se[r + 8] = __expf(phi);
        }
    }
    __syncthreads();

    float e = sm.se[tid];
    float s = e;
    #pragma unroll
    for (int o = 16; o; o >>= 1) s += __shfl_xor_sync(0xFFFFFFFFu, s, o);
    if (lane == 0) sm.wsum[wid] = s;
    __syncthreads();
    if (tid == 0)
        g_esum_part[blockIdx.x] = sm.wsum[0] + sm.wsum[1] + sm.wsum[2] + sm.wsum[3];

    // ---- fused pool over this CTA's 128 rows (x L2-hot, fp32).
    const int tc = tid >> 6;
    const int g  = tid & 63;
    const float* xb = x + (size_t)(row0 + tc * 64) * D_ + g * 4;

    float ax = 0.0f, ay = 0.0f, az = 0.0f, aw = 0.0f;
    #pragma unroll 16
    for (int tt = 0; tt < 64; ++tt) {
        float w  = sm.se[tc * 64 + tt];
        float4 v = *(const float4*)(xb + (size_t)tt * D_);
        ax += v.x * w; ay += v.y * w; az += v.z * w; aw += v.w * w;
    }
    if (tc == 1) {
        sm.pp[g][0] = ax; sm.pp[g][1] = ay; sm.pp[g][2] = az; sm.pp[g][3] = aw;
    }
    __syncthreads();
    if (tc == 0) {
        float4 r;
        r.x = ax + sm.pp[g][0];
        r.y = ay + sm.pp[g][1];
        r.z = az + sm.pp[g][2];
        r.w = aw + sm.pp[g][3];
        *(float4*)&g_pool_part[blockIdx.x * D_ + g * 4] = r;
    }

    // ---- last CTA of this batch finalizes out[b,:].
    __syncthreads();
    if (tid == 0) {
        __threadfence();
        int old = atomicAdd(&g_cnt[b], 1);
        sm.is_last = (old == 3);
    }
    __syncthreads();
    if (sm.is_last) {
        __threadfence();
        const float* ep = &g_esum_part[4 * b];
        float inv = 1.0f / (ep[0] + ep[1] + ep[2] + ep[3] + 1e-7f);
        int d = tid * 2;
        const float* pp = &g_pool_part[(4 * b) * D_ + d];
        float p0 = pp[0]     + pp[D_]     + pp[2 * D_]     + pp[3 * D_];
        float p1 = pp[1]     + pp[D_ + 1] + pp[2 * D_ + 1] + pp[3 * D_ + 1];
        float2 r;
        r.x = p0 * inv;
        r.y = p1 * inv;
        *(float2*)&out[b * D_ + d] = r;
    }
}

extern "C" void kernel_launch(void* const* d_in, const int* in_sizes, int n_in,
                              void* d_out, int out_size)
{
    const float* x  = (const float*)d_in[0];
    const float* W  = (const float*)d_in[1];
    const float* bb = (const float*)d_in[2];
    const float* u  = (const float*)d_in[3];
    float* out = (float*)d_out;

    prep_kernel<<<(NP * D_ + 511) / 512, 512>>>(W);
    score_pool_mma<<<(B_ * T_) / ROWS, 128>>>(x, bb, u, out);
}